// round 4
// baseline (speedup 1.0000x reference)
#include <cuda_runtime.h>
#include <math.h>

// ---------------- problem constants ----------------
#define B_  4
#define C_  192
#define T_  2048
#define H_  2
#define KC_ 96
#define FC_ 768
#define L_  6
#define SCALE_ 0.10206207261596577f   // 96^-0.5
#define EPS_ 1e-5f

// ---------------- scratch (no allocations allowed) ----------------
__device__ float g_x[B_*C_*T_];
__device__ float g_q[B_*C_*T_];
__device__ float g_k[B_*C_*T_];
__device__ float g_v[B_*C_*T_];
__device__ float g_a[B_*C_*T_];
__device__ float g_t[B_*C_*T_];
__device__ float g_f[B_*FC_*T_];
__device__ float g_m[B_*H_*T_];
__device__ float g_l[B_*H_*T_];

// ---------------- elementwise mask multiply ----------------
__global__ void k_maskmul(const float* __restrict__ in, const float* __restrict__ msk,
                          float* __restrict__ out)
{
    int idx = blockIdx.x * blockDim.x + threadIdx.x;
    if (idx >= B_*C_*T_) return;
    int b = idx / (C_*T_);
    int t = idx % T_;
    out[idx] = in[idx] * msk[b*T_ + t];
}

// ---------------- fused GEMM / 1-D conv ----------------
// Y[b,o,t] = osc * ( bias[o] + sum_{c,k} W[o,c,k] * X[b,c,t+k-pad] ), optional relu.
// X: [B, Cin, T_], W: [M, Cin, KW], Y: [B, M, T_].
template<int KW>
__global__ __launch_bounds__(256) void k_gemm(
    const float* __restrict__ X, const float* __restrict__ Wg,
    const float* __restrict__ bias, float* __restrict__ Y,
    int M, int Cin, int relu, float osc)
{
    constexpr int BM = 64, BN = 64, BK = 16;
    constexpr int PADW = (KW - 1) / 2;
    constexpr int BNH = BN + KW - 1;

    __shared__ float Ws[KW][BK][BM];
    __shared__ float Xs[BK][BNH];

    const int t0 = blockIdx.x * BN;
    const int m0 = blockIdx.y * BM;
    const int b  = blockIdx.z;
    const float* Xb = X + (size_t)b * Cin * T_;

    const int tid = threadIdx.x;
    const int tx = tid & 15, ty = tid >> 4;

    float acc[4][4] = {};

    for (int c0 = 0; c0 < Cin; c0 += BK) {
        // load weight tile (transposed to [k][c][o] for broadcast reads)
        for (int idx = tid; idx < BM*BK*KW; idx += 256) {
            int o  = idx / (BK*KW);
            int ck = idx - o * (BK*KW);
            int c  = ck / KW, k = ck - c * KW;
            Ws[k][c][o] = Wg[((size_t)(m0 + o) * Cin + c0 + c) * KW + k];
        }
        // load X tile with halo
        for (int idx = tid; idx < BK*BNH; idx += 256) {
            int c = idx / BNH, u = idx - c * BNH;
            int t = t0 - PADW + u;
            Xs[c][u] = (t >= 0 && t < T_) ? Xb[(size_t)(c0 + c) * T_ + t] : 0.f;
        }
        __syncthreads();

        #pragma unroll
        for (int cc = 0; cc < BK; cc++) {
            float bv[4 + KW - 1];
            #pragma unroll
            for (int u = 0; u < 4 + KW - 1; u++) bv[u] = Xs[cc][tx*4 + u];
            #pragma unroll
            for (int k = 0; k < KW; k++) {
                float4 a4 = *(const float4*)&Ws[k][cc][ty*4];
                float av[4] = {a4.x, a4.y, a4.z, a4.w};
                #pragma unroll
                for (int i = 0; i < 4; i++)
                    #pragma unroll
                    for (int j = 0; j < 4; j++)
                        acc[i][j] = fmaf(av[i], bv[j + k], acc[i][j]);
            }
        }
        __syncthreads();
    }

    #pragma unroll
    for (int i = 0; i < 4; i++) {
        int o = m0 + ty*4 + i;
        float bb = bias[o];
        float4 r;
        float* rp = reinterpret_cast<float*>(&r);
        #pragma unroll
        for (int j = 0; j < 4; j++) {
            float v = (acc[i][j] + bb) * osc;
            rp[j] = relu ? fmaxf(v, 0.f) : v;
        }
        *reinterpret_cast<float4*>(&Y[((size_t)b * M + o) * T_ + t0 + tx*4]) = r;
    }
}

// ---------------- flash attention with relative-K band ----------------
// Per (b,h): S[t,s] = SCALE*q[t]·k[s] + (|s-t|<=4 ? SCALE*q[t]·erk[s-t+4] : 0)
// online softmax; O[t,d] = sum_s P[t,s] v[s,d] / l[t]; saves m,l for rel-V pass.
__global__ __launch_bounds__(256) void k_flash(
    const float* __restrict__ Q, const float* __restrict__ Kp, const float* __restrict__ V,
    const float* __restrict__ erk, float* __restrict__ O,
    float* __restrict__ Mo, float* __restrict__ Lo)
{
    constexpr int BR = 64, BC = 64, D = 96, VS = 65; // VS: padded V row stride (bank-safe)
    extern __shared__ float sm[];
    float* Qs = sm;                 // D*BR
    float* Ks = Qs + D*BR;          // D*BC
    float* Vs = Ks + D*BC;          // D*VS
    float* Ps = Vs + D*VS;          // BR*BC
    float* qr = Ps + BR*BC;         // BR*9

    const int t0 = blockIdx.x * BR;
    const int h = blockIdx.y, b = blockIdx.z;
    const size_t base = ((size_t)b * C_ + h * KC_) * T_;
    const float* Qb = Q + base;
    const float* Kb = Kp + base;
    const float* Vb = V + base;

    const int tid = threadIdx.x;
    const int tx = tid & 15, ty = tid >> 4;

    for (int idx = tid; idx < D*BR; idx += 256) {
        int d = idx / BR, r = idx - d * BR;
        Qs[idx] = Qb[(size_t)d * T_ + t0 + r] * SCALE_;
    }
    __syncthreads();
    // q · erk  (scaled q already)
    for (int idx = tid; idx < BR * 9; idx += 256) {
        int r = idx / 9, dd = idx - r * 9;
        float s = 0.f;
        #pragma unroll 8
        for (int d = 0; d < D; d++) s = fmaf(Qs[d*BR + r], erk[dd*KC_ + d], s);
        qr[idx] = s;
    }

    float m_i[4], l_i[4], oa[4][6];
    #pragma unroll
    for (int i = 0; i < 4; i++) {
        m_i[i] = -1e30f; l_i[i] = 0.f;
        #pragma unroll
        for (int j = 0; j < 6; j++) oa[i][j] = 0.f;
    }

    for (int s0 = 0; s0 < T_; s0 += BC) {
        __syncthreads();  // previous O-phase done reading Ks/Vs/Ps
        for (int idx = tid; idx < D*BC; idx += 256) {
            int d = idx / BC, c = idx - d * BC;
            Ks[d*BC + c] = Kb[(size_t)d * T_ + s0 + c];
            Vs[d*VS + c] = Vb[(size_t)d * T_ + s0 + c];
        }
        __syncthreads();

        float sc[4][4] = {};
        #pragma unroll 4
        for (int d = 0; d < D; d++) {
            float4 a4 = *(const float4*)&Qs[d*BR + ty*4];
            float4 b4 = *(const float4*)&Ks[d*BC + tx*4];
            float av[4] = {a4.x, a4.y, a4.z, a4.w};
            float bv[4] = {b4.x, b4.y, b4.z, b4.w};
            #pragma unroll
            for (int i = 0; i < 4; i++)
                #pragma unroll
                for (int j = 0; j < 4; j++)
                    sc[i][j] = fmaf(av[i], bv[j], sc[i][j]);
        }

        // relative-K band (only near-diagonal tiles)
        if (s0 + BC + 4 > t0 && s0 < t0 + BR + 5) {
            #pragma unroll
            for (int i = 0; i < 4; i++)
                #pragma unroll
                for (int j = 0; j < 4; j++) {
                    int delta = (s0 + tx*4 + j) - (t0 + ty*4 + i);
                    if (delta >= -4 && delta <= 4)
                        sc[i][j] += qr[(ty*4 + i)*9 + delta + 4];
                }
        }

        // online softmax (row reduce across 16 tx lanes)
        #pragma unroll
        for (int i = 0; i < 4; i++) {
            float mx = fmaxf(fmaxf(sc[i][0], sc[i][1]), fmaxf(sc[i][2], sc[i][3]));
            #pragma unroll
            for (int off = 8; off; off >>= 1)
                mx = fmaxf(mx, __shfl_xor_sync(0xffffffffu, mx, off));
            float mn = fmaxf(m_i[i], mx);
            float al = __expf(m_i[i] - mn);
            float p0 = __expf(sc[i][0] - mn), p1 = __expf(sc[i][1] - mn);
            float p2 = __expf(sc[i][2] - mn), p3 = __expf(sc[i][3] - mn);
            *(float4*)&Ps[(ty*4 + i)*BC + tx*4] = make_float4(p0, p1, p2, p3);
            float rs = p0 + p1 + p2 + p3;
            #pragma unroll
            for (int off = 8; off; off >>= 1)
                rs += __shfl_xor_sync(0xffffffffu, rs, off);
            l_i[i] = l_i[i] * al + rs;
            m_i[i] = mn;
            #pragma unroll
            for (int j = 0; j < 6; j++) oa[i][j] *= al;
        }
        __syncthreads();

        // O += P @ V^T   (thread owns rows ty*4+i, d-cols tx*6+j)
        #pragma unroll 4
        for (int s = 0; s < BC; s++) {
            float pv[4];
            #pragma unroll
            for (int i = 0; i < 4; i++) pv[i] = Ps[(ty*4 + i)*BC + s];
            float vv[6];
            #pragma unroll
            for (int j = 0; j < 6; j++) vv[j] = Vs[(tx*6 + j)*VS + s];
            #pragma unroll
            for (int i = 0; i < 4; i++)
                #pragma unroll
                for (int j = 0; j < 6; j++)
                    oa[i][j] = fmaf(pv[i], vv[j], oa[i][j]);
        }
    }
    __syncthreads();

    // normalize + stage through smem for coalesced store
    #pragma unroll
    for (int i = 0; i < 4; i++) {
        float inv = 1.f / l_i[i];
        #pragma unroll
        for (int j = 0; j < 6; j++)
            Qs[(tx*6 + j)*BR + ty*4 + i] = oa[i][j] * inv;
    }
    if (tx == 0) {
        #pragma unroll
        for (int i = 0; i < 4; i++) {
            int t = t0 + ty*4 + i;
            Mo[((size_t)b*H_ + h)*T_ + t] = m_i[i];
            Lo[((size_t)b*H_ + h)*T_ + t] = l_i[i];
        }
    }
    __syncthreads();
    float* Ob = O + base;
    for (int idx = tid; idx < D*BR; idx += 256) {
        int d = idx / BR, r = idx - d * BR;
        Ob[(size_t)d * T_ + t0 + r] = Qs[idx];
    }
}

// ---------------- relative-V band correction ----------------
// out[t,d] += sum_{delta=-4..4, valid} p[t,t+delta] * erv[delta+4, d]
// p reconstructed exactly from saved (m, l).
__global__ __launch_bounds__(256) void k_relv(
    const float* __restrict__ Q, const float* __restrict__ Kp,
    const float* __restrict__ erk, const float* __restrict__ erv,
    const float* __restrict__ Mo, const float* __restrict__ Lo,
    float* __restrict__ O)
{
    __shared__ float Qt[96*32];
    __shared__ float Kt[96*40];
    __shared__ float ek[9*96], ev[9*96];

    const int t0 = blockIdx.x * 32;
    const int h = blockIdx.y, b = blockIdx.z;
    const size_t base = ((size_t)b * C_ + h * KC_) * T_;
    const int tid = threadIdx.x;

    for (int idx = tid; idx < 96*32; idx += 256) {
        int d = idx / 32, u = idx - d * 32;
        Qt[idx] = Q[base + (size_t)d * T_ + t0 + u] * SCALE_;
    }
    for (int idx = tid; idx < 96*40; idx += 256) {
        int d = idx / 40, u = idx - d * 40;
        int t = t0 - 4 + u;
        Kt[idx] = (t >= 0 && t < T_) ? Kp[base + (size_t)d * T_ + t] : 0.f;
    }
    for (int idx = tid; idx < 9*96; idx += 256) { ek[idx] = erk[idx]; ev[idx] = erv[idx]; }
    __syncthreads();

    const int tx = tid & 31, g = tid >> 5;     // 32 t-lanes x 8 d-groups
    const int t = t0 + tx;
    const float m = Mo[((size_t)b*H_ + h)*T_ + t];
    const float invl = 1.f / Lo[((size_t)b*H_ + h)*T_ + t];

    float p[9];
    #pragma unroll
    for (int dd = 0; dd < 9; dd++) {
        int s = t + dd - 4;
        if (s < 0 || s >= T_) { p[dd] = 0.f; continue; }
        float sc = 0.f;
        #pragma unroll 8
        for (int d = 0; d < 96; d++)
            sc = fmaf(Qt[d*32 + tx], Kt[d*40 + tx + dd] + ek[dd*96 + d], sc);
        p[dd] = __expf(sc - m) * invl;
    }
    #pragma unroll
    for (int jd = 0; jd < 12; jd++) {
        int d = g * 12 + jd;
        float add = 0.f;
        #pragma unroll
        for (int dd = 0; dd < 9; dd++) add = fmaf(p[dd], ev[dd*96 + d], add);
        O[base + (size_t)d * T_ + t] += add;
    }
}

// ---------------- fused residual-add + channel LayerNorm ----------------
// x = LN(x + r) over C, per (b,t).  block (32 t-lanes, 8 c-groups)
__global__ __launch_bounds__(256) void k_addln(
    float* __restrict__ X, const float* __restrict__ R,
    const float* __restrict__ gg, const float* __restrict__ be)
{
    const int tx = threadIdx.x, ty = threadIdx.y;
    const int t = blockIdx.x * 32 + tx;
    const int b = blockIdx.y;

    float vals[24];
    float s = 0.f, sq = 0.f;
    #pragma unroll
    for (int k = 0; k < 24; k++) {
        int c = ty + k * 8;
        size_t idx = ((size_t)b * C_ + c) * T_ + t;
        float v = X[idx] + R[idx];
        vals[k] = v; s += v; sq += v * v;
    }
    __shared__ float ss[8][33], sg[8][33];
    ss[ty][tx] = s; sg[ty][tx] = sq;
    __syncthreads();
    if (ty == 0) {
        float a = 0.f, q = 0.f;
        #pragma unroll
        for (int k = 0; k < 8; k++) { a += ss[k][tx]; q += sg[k][tx]; }
        ss[0][tx] = a; sg[0][tx] = q;
    }
    __syncthreads();
    const float mean = ss[0][tx] * (1.f / C_);
    const float var  = sg[0][tx] * (1.f / C_) - mean * mean;
    const float rstd = rsqrtf(var + EPS_);
    #pragma unroll
    for (int k = 0; k < 24; k++) {
        int c = ty + k * 8;
        size_t idx = ((size_t)b * C_ + c) * T_ + t;
        X[idx] = (vals[k] - mean) * rstd * gg[c] + be[c];
    }
}

// ---------------- launcher ----------------
extern "C" void kernel_launch(void* const* d_in, const int* in_sizes, int n_in,
                              void* d_out, int out_size)
{
    (void)in_sizes; (void)n_in; (void)out_size;
    const float* x   = (const float*)d_in[0];
    const float* msk = (const float*)d_in[1];
    const float* Wq  = (const float*)d_in[2];
    const float* bq  = (const float*)d_in[3];
    const float* Wk  = (const float*)d_in[4];
    const float* bk  = (const float*)d_in[5];
    const float* Wv  = (const float*)d_in[6];
    const float* bv  = (const float*)d_in[7];
    const float* Wo  = (const float*)d_in[8];
    const float* bo  = (const float*)d_in[9];
    const float* erk = (const float*)d_in[10];
    const float* erv = (const float*)d_in[11];
    const float* g1  = (const float*)d_in[12];
    const float* be1 = (const float*)d_in[13];
    const float* fw1 = (const float*)d_in[14];
    const float* fb1 = (const float*)d_in[15];
    const float* fw2 = (const float*)d_in[16];
    const float* fb2 = (const float*)d_in[17];
    const float* g2  = (const float*)d_in[18];
    const float* be2 = (const float*)d_in[19];

    float *xb, *qb, *kb, *vb, *ab, *tb, *fb, *mb, *lb;
    cudaGetSymbolAddress((void**)&xb, g_x);
    cudaGetSymbolAddress((void**)&qb, g_q);
    cudaGetSymbolAddress((void**)&kb, g_k);
    cudaGetSymbolAddress((void**)&vb, g_v);
    cudaGetSymbolAddress((void**)&ab, g_a);
    cudaGetSymbolAddress((void**)&tb, g_t);
    cudaGetSymbolAddress((void**)&fb, g_f);
    cudaGetSymbolAddress((void**)&mb, g_m);
    cudaGetSymbolAddress((void**)&lb, g_l);

    constexpr int FLASH_SMEM = (96*64 + 96*64 + 96*65 + 64*64 + 64*9) * 4;
    cudaFuncSetAttribute(k_flash, cudaFuncAttributeMaxDynamicSharedMemorySize, FLASH_SMEM);

    k_maskmul<<<(B_*C_*T_ + 255)/256, 256>>>(x, msk, xb);

    for (int i = 0; i < L_; i++) {
        dim3 gp(T_/64, C_/64, B_);
        k_gemm<1><<<gp, 256>>>(xb, Wq + (size_t)i*C_*C_, bq + i*C_, qb, C_, C_, 0, 1.f);
        k_gemm<1><<<gp, 256>>>(xb, Wk + (size_t)i*C_*C_, bk + i*C_, kb, C_, C_, 0, 1.f);
        k_gemm<1><<<gp, 256>>>(xb, Wv + (size_t)i*C_*C_, bv + i*C_, vb, C_, C_, 0, 1.f);

        k_flash<<<dim3(T_/64, H_, B_), 256, FLASH_SMEM>>>(
            qb, kb, vb, erk + (size_t)i*9*KC_, ab, mb, lb);
        k_relv<<<dim3(T_/32, H_, B_), 256>>>(
            qb, kb, erk + (size_t)i*9*KC_, erv + (size_t)i*9*KC_, mb, lb, ab);

        k_gemm<1><<<gp, 256>>>(ab, Wo + (size_t)i*C_*C_, bo + i*C_, tb, C_, C_, 0, 1.f);
        k_addln<<<dim3(T_/32, B_), dim3(32, 8)>>>(xb, tb, g1 + i*C_, be1 + i*C_);

        k_gemm<3><<<dim3(T_/64, FC_/64, B_), 256>>>(
            xb, fw1 + (size_t)i*FC_*C_*3, fb1 + i*FC_, fb, FC_, C_, 1, 1.f);
        k_gemm<3><<<dim3(T_/64, C_/64, B_), 256>>>(
            fb, fw2 + (size_t)i*C_*FC_*3, fb2 + i*C_, tb, C_, FC_, 0, 1.f);
        k_addln<<<dim3(T_/32, B_), dim3(32, 8)>>>(xb, tb, g2 + i*C_, be2 + i*C_);
    }

    k_maskmul<<<(B_*C_*T_ + 255)/256, 256>>>(xb, msk, (float*)d_out);
}

// round 5
// speedup vs baseline: 1.1231x; 1.1231x over previous
#include <cuda_runtime.h>
#include <math.h>

// ---------------- problem constants ----------------
#define B_  4
#define C_  192
#define T_  2048
#define H_  2
#define KC_ 96
#define FC_ 768
#define L_  6
#define SCALE_ 0.10206207261596577f   // 96^-0.5
#define EPS_ 1e-5f

// ---------------- packed f32x2 helpers (Blackwell FFMA2 path) ----------------
typedef unsigned long long ull;
__device__ __forceinline__ ull ffma2(ull a, ull b, ull c) {
    ull d; asm("fma.rn.f32x2 %0, %1, %2, %3;" : "=l"(d) : "l"(a), "l"(b), "l"(c));
    return d;
}
__device__ __forceinline__ ull fmul2(ull a, ull b) {
    ull d; asm("mul.rn.f32x2 %0, %1, %2;" : "=l"(d) : "l"(a), "l"(b));
    return d;
}
__device__ __forceinline__ ull fdup(float x) {
    ull r; asm("mov.b64 %0, {%1, %2};" : "=l"(r) : "f"(x), "f"(x));
    return r;
}
__device__ __forceinline__ ull fpack(float lo, float hi) {
    ull r; asm("mov.b64 %0, {%1, %2};" : "=l"(r) : "f"(lo), "f"(hi));
    return r;
}
__device__ __forceinline__ float2 funpack(ull v) {
    float2 f; asm("mov.b64 {%0, %1}, %2;" : "=f"(f.x), "=f"(f.y) : "l"(v));
    return f;
}

// ---------------- scratch (no allocations allowed) ----------------
__device__ float g_x[B_*C_*T_];
__device__ float g_q[B_*C_*T_];
__device__ float g_k[B_*C_*T_];
__device__ float g_v[B_*C_*T_];
__device__ float g_a[B_*C_*T_];
__device__ float g_t[B_*C_*T_];
__device__ float g_f[B_*FC_*T_];
__device__ float g_m[B_*H_*T_];
__device__ float g_l[B_*H_*T_];

// ---------------- elementwise mask multiply ----------------
__global__ void k_maskmul(const float* __restrict__ in, const float* __restrict__ msk,
                          float* __restrict__ out)
{
    int idx = blockIdx.x * blockDim.x + threadIdx.x;
    if (idx >= B_*C_*T_) return;
    int b = idx / (C_*T_);
    int t = idx % T_;
    out[idx] = in[idx] * msk[b*T_ + t];
}

// ---------------- fused GEMM / 1-D conv, FFMA2 microkernel ----------------
// Y[b,o,t] = bias[o] + sum_{c,k} W[o,c,k] * X[b,c,t+k-pad], optional relu.
// 128 threads, BM=BN=64, per-thread 8 rows x 4 cols (2 packed pairs).
template<int KW>
__global__ __launch_bounds__(128) void k_gemm(
    const float* __restrict__ X, const float* __restrict__ Wg,
    const float* __restrict__ bias, float* __restrict__ Y,
    int M, int Cin, int relu)
{
    constexpr int BM = 64, BN = 64, BK = 16;
    constexpr int PADW = (KW - 1) / 2;
    constexpr int XV = BN + KW - 1;      // valid halo width
    constexpr int XW = 68;               // padded row stride (float4-safe)

    __shared__ float Ws[KW][BK][XW];     // [k][c][o] with padded o-stride
    __shared__ float Xs[BK][XW];

    const int t0 = blockIdx.x * BN;
    const int m0 = blockIdx.y * BM;
    const int b  = blockIdx.z;
    const float* Xb = X + (size_t)b * Cin * T_;

    const int tid = threadIdx.x;
    const int tx = tid & 15, ty = tid >> 4;   // tx: 16 x 4 cols, ty: 8 x 8 rows

    ull acc[8][2] = {};

    for (int c0 = 0; c0 < Cin; c0 += BK) {
        for (int idx = tid; idx < BM*BK*KW; idx += 128) {
            int o  = idx / (BK*KW);
            int ck = idx - o * (BK*KW);
            int c  = ck / KW, k = ck - c * KW;
            Ws[k][c][o] = Wg[((size_t)(m0 + o) * Cin + c0 + c) * KW + k];
        }
        for (int idx = tid; idx < BK*XV; idx += 128) {
            int c = idx / XV, u = idx - c * XV;
            int t = t0 - PADW + u;
            Xs[c][u] = (t >= 0 && t < T_) ? Xb[(size_t)(c0 + c) * T_ + t] : 0.f;
        }
        __syncthreads();

        #pragma unroll
        for (int cc = 0; cc < BK; cc++) {
            float4 xb0 = *(const float4*)&Xs[cc][tx*4];
            float xb4 = 0.f, xb5 = 0.f;
            if (KW == 3) { xb4 = Xs[cc][tx*4 + 4]; xb5 = Xs[cc][tx*4 + 5]; }

            #pragma unroll
            for (int k = 0; k < KW; k++) {
                ull bp0, bp1;
                if (k == 0)      { bp0 = fpack(xb0.x, xb0.y); bp1 = fpack(xb0.z, xb0.w); }
                else if (k == 1) { bp0 = fpack(xb0.y, xb0.z); bp1 = fpack(xb0.w, xb4);   }
                else             { bp0 = fpack(xb0.z, xb0.w); bp1 = fpack(xb4,   xb5);   }

                float4 a0 = *(const float4*)&Ws[k][cc][ty*8];
                float4 a1 = *(const float4*)&Ws[k][cc][ty*8 + 4];
                float av[8] = {a0.x, a0.y, a0.z, a0.w, a1.x, a1.y, a1.z, a1.w};
                #pragma unroll
                for (int i = 0; i < 8; i++) {
                    ull ad = fdup(av[i]);
                    acc[i][0] = ffma2(ad, bp0, acc[i][0]);
                    acc[i][1] = ffma2(ad, bp1, acc[i][1]);
                }
            }
        }
        __syncthreads();
    }

    #pragma unroll
    for (int i = 0; i < 8; i++) {
        int o = m0 + ty*8 + i;
        float bb = bias[o];
        float2 lo = funpack(acc[i][0]);
        float2 hi = funpack(acc[i][1]);
        float4 r = make_float4(lo.x + bb, lo.y + bb, hi.x + bb, hi.y + bb);
        if (relu) {
            r.x = fmaxf(r.x, 0.f); r.y = fmaxf(r.y, 0.f);
            r.z = fmaxf(r.z, 0.f); r.w = fmaxf(r.w, 0.f);
        }
        *reinterpret_cast<float4*>(&Y[((size_t)b * M + o) * T_ + t0 + tx*4]) = r;
    }
}

// ---------------- flash attention with relative-K band (FFMA2) ----------------
__global__ __launch_bounds__(256) void k_flash(
    const float* __restrict__ Q, const float* __restrict__ Kp, const float* __restrict__ V,
    const float* __restrict__ erk, float* __restrict__ O,
    float* __restrict__ Mo, float* __restrict__ Lo)
{
    constexpr int BR = 64, BC = 64, D = 96, VSTR = 98; // V stored [s][d], padded stride
    extern __shared__ float sm[];
    float* Qs = sm;                 // D*BR     [d][r]
    float* Ks = Qs + D*BR;          // D*BC     [d][c]
    float* Vs = Ks + D*BC;          // BC*VSTR  [s][d]
    float* Ps = Vs + BC*VSTR;       // BR*BC
    float* qr = Ps + BR*BC;         // BR*9

    const int t0 = blockIdx.x * BR;
    const int h = blockIdx.y, b = blockIdx.z;
    const size_t base = ((size_t)b * C_ + h * KC_) * T_;
    const float* Qb = Q + base;
    const float* Kb = Kp + base;
    const float* Vb = V + base;

    const int tid = threadIdx.x;
    const int tx = tid & 15, ty = tid >> 4;

    for (int idx = tid; idx < D*BR; idx += 256) {
        int d = idx / BR, r = idx - d * BR;
        Qs[idx] = Qb[(size_t)d * T_ + t0 + r] * SCALE_;
    }
    __syncthreads();
    // q · erk  (scaled q already)
    for (int idx = tid; idx < BR * 9; idx += 256) {
        int r = idx / 9, dd = idx - r * 9;
        float s = 0.f;
        #pragma unroll 8
        for (int d = 0; d < D; d++) s = fmaf(Qs[d*BR + r], erk[dd*KC_ + d], s);
        qr[idx] = s;
    }

    float m_i[4], l_i[4];
    ull oa[4][3];
    #pragma unroll
    for (int i = 0; i < 4; i++) {
        m_i[i] = -1e30f; l_i[i] = 0.f;
        #pragma unroll
        for (int j = 0; j < 3; j++) oa[i][j] = 0ull;
    }

    for (int s0 = 0; s0 < T_; s0 += BC) {
        __syncthreads();  // previous phase done reading Ks/Vs/Ps
        for (int idx = tid; idx < D*BC; idx += 256) {
            int d = idx / BC, c = idx - d * BC;
            Ks[d*BC + c] = Kb[(size_t)d * T_ + s0 + c];
            Vs[c*VSTR + d] = Vb[(size_t)d * T_ + s0 + c];
        }
        __syncthreads();

        // S = Q K^T  (packed pairs along cols)
        ull sc2[4][2] = {};
        #pragma unroll 4
        for (int d = 0; d < D; d++) {
            float4 a4 = *(const float4*)&Qs[d*BR + ty*4];
            float4 b4 = *(const float4*)&Ks[d*BC + tx*4];
            ull bp0 = fpack(b4.x, b4.y), bp1 = fpack(b4.z, b4.w);
            float av[4] = {a4.x, a4.y, a4.z, a4.w};
            #pragma unroll
            for (int i = 0; i < 4; i++) {
                ull ad = fdup(av[i]);
                sc2[i][0] = ffma2(ad, bp0, sc2[i][0]);
                sc2[i][1] = ffma2(ad, bp1, sc2[i][1]);
            }
        }
        float sc[4][4];
        #pragma unroll
        for (int i = 0; i < 4; i++) {
            float2 lo = funpack(sc2[i][0]), hi = funpack(sc2[i][1]);
            sc[i][0] = lo.x; sc[i][1] = lo.y; sc[i][2] = hi.x; sc[i][3] = hi.y;
        }

        // relative-K band (only near-diagonal tiles)
        if (s0 + BC + 4 > t0 && s0 < t0 + BR + 5) {
            #pragma unroll
            for (int i = 0; i < 4; i++)
                #pragma unroll
                for (int j = 0; j < 4; j++) {
                    int delta = (s0 + tx*4 + j) - (t0 + ty*4 + i);
                    if (delta >= -4 && delta <= 4)
                        sc[i][j] += qr[(ty*4 + i)*9 + delta + 4];
                }
        }

        // online softmax (row reduce across 16 tx lanes)
        #pragma unroll
        for (int i = 0; i < 4; i++) {
            float mx = fmaxf(fmaxf(sc[i][0], sc[i][1]), fmaxf(sc[i][2], sc[i][3]));
            #pragma unroll
            for (int off = 8; off; off >>= 1)
                mx = fmaxf(mx, __shfl_xor_sync(0xffffffffu, mx, off));
            float mn = fmaxf(m_i[i], mx);
            float al = __expf(m_i[i] - mn);
            float p0 = __expf(sc[i][0] - mn), p1 = __expf(sc[i][1] - mn);
            float p2 = __expf(sc[i][2] - mn), p3 = __expf(sc[i][3] - mn);
            *(float4*)&Ps[(ty*4 + i)*BC + tx*4] = make_float4(p0, p1, p2, p3);
            float rs = p0 + p1 + p2 + p3;
            #pragma unroll
            for (int off = 8; off; off >>= 1)
                rs += __shfl_xor_sync(0xffffffffu, rs, off);
            l_i[i] = l_i[i] * al + rs;
            m_i[i] = mn;
            ull al2 = fdup(al);
            #pragma unroll
            for (int j = 0; j < 3; j++) oa[i][j] = fmul2(oa[i][j], al2);
        }
        __syncthreads();

        // O += P @ V  (thread owns rows ty*4+i, d-cols tx*6 .. +5 as 3 pairs)
        #pragma unroll 2
        for (int s = 0; s < BC; s++) {
            ull pd[4];
            #pragma unroll
            for (int i = 0; i < 4; i++) pd[i] = fdup(Ps[(ty*4 + i)*BC + s]);
            const float* vrow = &Vs[s*VSTR + tx*6];
            ull v0 = *(const ull*)(vrow);
            ull v1 = *(const ull*)(vrow + 2);
            ull v2 = *(const ull*)(vrow + 4);
            #pragma unroll
            for (int i = 0; i < 4; i++) {
                oa[i][0] = ffma2(pd[i], v0, oa[i][0]);
                oa[i][1] = ffma2(pd[i], v1, oa[i][1]);
                oa[i][2] = ffma2(pd[i], v2, oa[i][2]);
            }
        }
    }
    __syncthreads();

    // normalize + stage through smem for coalesced store
    #pragma unroll
    for (int i = 0; i < 4; i++) {
        float inv = 1.f / l_i[i];
        #pragma unroll
        for (int j = 0; j < 3; j++) {
            float2 p = funpack(oa[i][j]);
            Qs[(tx*6 + j*2    )*BR + ty*4 + i] = p.x * inv;
            Qs[(tx*6 + j*2 + 1)*BR + ty*4 + i] = p.y * inv;
        }
    }
    if (tx == 0) {
        #pragma unroll
        for (int i = 0; i < 4; i++) {
            int t = t0 + ty*4 + i;
            Mo[((size_t)b*H_ + h)*T_ + t] = m_i[i];
            Lo[((size_t)b*H_ + h)*T_ + t] = l_i[i];
        }
    }
    __syncthreads();
    float* Ob = O + base;
    for (int idx = tid; idx < D*BR; idx += 256) {
        int d = idx / BR, r = idx - d * BR;
        Ob[(size_t)d * T_ + t0 + r] = Qs[idx];
    }
}

// ---------------- relative-V band correction ----------------
__global__ __launch_bounds__(256) void k_relv(
    const float* __restrict__ Q, const float* __restrict__ Kp,
    const float* __restrict__ erk, const float* __restrict__ erv,
    const float* __restrict__ Mo, const float* __restrict__ Lo,
    float* __restrict__ O)
{
    __shared__ float Qt[96*32];
    __shared__ float Kt[96*40];
    __shared__ float ek[9*96], ev[9*96];

    const int t0 = blockIdx.x * 32;
    const int h = blockIdx.y, b = blockIdx.z;
    const size_t base = ((size_t)b * C_ + h * KC_) * T_;
    const int tid = threadIdx.x;

    for (int idx = tid; idx < 96*32; idx += 256) {
        int d = idx / 32, u = idx - d * 32;
        Qt[idx] = Q[base + (size_t)d * T_ + t0 + u] * SCALE_;
    }
    for (int idx = tid; idx < 96*40; idx += 256) {
        int d = idx / 40, u = idx - d * 40;
        int t = t0 - 4 + u;
        Kt[idx] = (t >= 0 && t < T_) ? Kp[base + (size_t)d * T_ + t] : 0.f;
    }
    for (int idx = tid; idx < 9*96; idx += 256) { ek[idx] = erk[idx]; ev[idx] = erv[idx]; }
    __syncthreads();

    const int tx = tid & 31, g = tid >> 5;     // 32 t-lanes x 8 d-groups
    const int t = t0 + tx;
    const float m = Mo[((size_t)b*H_ + h)*T_ + t];
    const float invl = 1.f / Lo[((size_t)b*H_ + h)*T_ + t];

    float p[9];
    #pragma unroll
    for (int dd = 0; dd < 9; dd++) {
        int s = t + dd - 4;
        if (s < 0 || s >= T_) { p[dd] = 0.f; continue; }
        float sc = 0.f;
        #pragma unroll 8
        for (int d = 0; d < 96; d++)
            sc = fmaf(Qt[d*32 + tx], Kt[d*40 + tx + dd] + ek[dd*96 + d], sc);
        p[dd] = __expf(sc - m) * invl;
    }
    #pragma unroll
    for (int jd = 0; jd < 12; jd++) {
        int d = g * 12 + jd;
        float add = 0.f;
        #pragma unroll
        for (int dd = 0; dd < 9; dd++) add = fmaf(p[dd], ev[dd*96 + d], add);
        O[base + (size_t)d * T_ + t] += add;
    }
}

// ---------------- fused residual-add + channel LayerNorm ----------------
__global__ __launch_bounds__(256) void k_addln(
    float* __restrict__ X, const float* __restrict__ R,
    const float* __restrict__ gg, const float* __restrict__ be)
{
    const int tx = threadIdx.x, ty = threadIdx.y;
    const int t = blockIdx.x * 32 + tx;
    const int b = blockIdx.y;

    float vals[24];
    float s = 0.f, sq = 0.f;
    #pragma unroll
    for (int k = 0; k < 24; k++) {
        int c = ty + k * 8;
        size_t idx = ((size_t)b * C_ + c) * T_ + t;
        float v = X[idx] + R[idx];
        vals[k] = v; s += v; sq += v * v;
    }
    __shared__ float ss[8][33], sg[8][33];
    ss[ty][tx] = s; sg[ty][tx] = sq;
    __syncthreads();
    if (ty == 0) {
        float a = 0.f, q = 0.f;
        #pragma unroll
        for (int k = 0; k < 8; k++) { a += ss[k][tx]; q += sg[k][tx]; }
        ss[0][tx] = a; sg[0][tx] = q;
    }
    __syncthreads();
    const float mean = ss[0][tx] * (1.f / C_);
    const float var  = sg[0][tx] * (1.f / C_) - mean * mean;
    const float rstd = rsqrtf(var + EPS_);
    #pragma unroll
    for (int k = 0; k < 24; k++) {
        int c = ty + k * 8;
        size_t idx = ((size_t)b * C_ + c) * T_ + t;
        X[idx] = (vals[k] - mean) * rstd * gg[c] + be[c];
    }
}

// ---------------- launcher ----------------
extern "C" void kernel_launch(void* const* d_in, const int* in_sizes, int n_in,
                              void* d_out, int out_size)
{
    (void)in_sizes; (void)n_in; (void)out_size;
    const float* x   = (const float*)d_in[0];
    const float* msk = (const float*)d_in[1];
    const float* Wq  = (const float*)d_in[2];
    const float* bq  = (const float*)d_in[3];
    const float* Wk  = (const float*)d_in[4];
    const float* bk  = (const float*)d_in[5];
    const float* Wv  = (const float*)d_in[6];
    const float* bv  = (const float*)d_in[7];
    const float* Wo  = (const float*)d_in[8];
    const float* bo  = (const float*)d_in[9];
    const float* erk = (const float*)d_in[10];
    const float* erv = (const float*)d_in[11];
    const float* g1  = (const float*)d_in[12];
    const float* be1 = (const float*)d_in[13];
    const float* fw1 = (const float*)d_in[14];
    const float* fb1 = (const float*)d_in[15];
    const float* fw2 = (const float*)d_in[16];
    const float* fb2 = (const float*)d_in[17];
    const float* g2  = (const float*)d_in[18];
    const float* be2 = (const float*)d_in[19];

    float *xb, *qb, *kb, *vb, *ab, *tb, *fb, *mb, *lb;
    cudaGetSymbolAddress((void**)&xb, g_x);
    cudaGetSymbolAddress((void**)&qb, g_q);
    cudaGetSymbolAddress((void**)&kb, g_k);
    cudaGetSymbolAddress((void**)&vb, g_v);
    cudaGetSymbolAddress((void**)&ab, g_a);
    cudaGetSymbolAddress((void**)&tb, g_t);
    cudaGetSymbolAddress((void**)&fb, g_f);
    cudaGetSymbolAddress((void**)&mb, g_m);
    cudaGetSymbolAddress((void**)&lb, g_l);

    constexpr int FLASH_SMEM = (96*64 + 96*64 + 64*98 + 64*64 + 64*9) * 4;
    cudaFuncSetAttribute(k_flash, cudaFuncAttributeMaxDynamicSharedMemorySize, FLASH_SMEM);

    k_maskmul<<<(B_*C_*T_ + 255)/256, 256>>>(x, msk, xb);

    for (int i = 0; i < L_; i++) {
        dim3 gp(T_/64, C_/64, B_);
        k_gemm<1><<<gp, 128>>>(xb, Wq + (size_t)i*C_*C_, bq + i*C_, qb, C_, C_, 0);
        k_gemm<1><<<gp, 128>>>(xb, Wk + (size_t)i*C_*C_, bk + i*C_, kb, C_, C_, 0);
        k_gemm<1><<<gp, 128>>>(xb, Wv + (size_t)i*C_*C_, bv + i*C_, vb, C_, C_, 0);

        k_flash<<<dim3(T_/64, H_, B_), 256, FLASH_SMEM>>>(
            qb, kb, vb, erk + (size_t)i*9*KC_, ab, mb, lb);
        k_relv<<<dim3(T_/32, H_, B_), 256>>>(
            qb, kb, erk + (size_t)i*9*KC_, erv + (size_t)i*9*KC_, mb, lb, ab);

        k_gemm<1><<<gp, 128>>>(ab, Wo + (size_t)i*C_*C_, bo + i*C_, tb, C_, C_, 0);
        k_addln<<<dim3(T_/32, B_), dim3(32, 8)>>>(xb, tb, g1 + i*C_, be1 + i*C_);

        k_gemm<3><<<dim3(T_/64, FC_/64, B_), 128>>>(
            xb, fw1 + (size_t)i*FC_*C_*3, fb1 + i*FC_, fb, FC_, C_, 1);
        k_gemm<3><<<dim3(T_/64, C_/64, B_), 128>>>(
            fb, fw2 + (size_t)i*C_*FC_*3, fb2 + i*C_, tb, C_, FC_, 0);
        k_addln<<<dim3(T_/32, B_), dim3(32, 8)>>>(xb, tb, g2 + i*C_, be2 + i*C_);
    }

    k_maskmul<<<(B_*C_*T_ + 255)/256, 256>>>(xb, msk, (float*)d_out);
}